// round 1
// baseline (speedup 1.0000x reference)
#include <cuda_runtime.h>
#include <cuda_bf16.h>
#include <math.h>

// Problem constants
#define LAYERS 6
#define BATCH  4
#define SEQ    512
#define DIM    1024
#define HEADS  16
#define DHEAD  64
#define FFN    4096
#define TOKENS (BATCH*SEQ)          // 2048
#define ID     (HEADS*DHEAD)        // 1024

// ---------------- scratch (allocation-guard safe) ----------------
__device__ float g_h  [TOKENS*DIM];     // LN output
__device__ float g_qkv[TOKENS*3*ID];    // qkv
__device__ float g_o  [TOKENS*ID];      // attention output
__device__ float g_a  [TOKENS*FFN];     // FF hidden

// ---------------- LayerNorm ----------------
__global__ __launch_bounds__(256) void ln_kernel(
    const float* __restrict__ x, const float* __restrict__ scale,
    const float* __restrict__ bias, float* __restrict__ out)
{
    __shared__ float wsum[8], wsq[8];
    int row = blockIdx.x, t = threadIdx.x;
    const float4* xr = (const float4*)(x + (size_t)row * DIM);
    float4 v = xr[t];
    float s  = v.x + v.y + v.z + v.w;
    float ss = v.x*v.x + v.y*v.y + v.z*v.z + v.w*v.w;
    #pragma unroll
    for (int o = 16; o; o >>= 1) {
        s  += __shfl_xor_sync(0xffffffffu, s,  o);
        ss += __shfl_xor_sync(0xffffffffu, ss, o);
    }
    if ((t & 31) == 0) { wsum[t >> 5] = s; wsq[t >> 5] = ss; }
    __syncthreads();
    float S = 0.f, SS = 0.f;
    #pragma unroll
    for (int i = 0; i < 8; i++) { S += wsum[i]; SS += wsq[i]; }
    float mean = S * (1.0f / DIM);
    float var  = SS * (1.0f / DIM) - mean * mean;
    float rstd = rsqrtf(var + 1e-5f);
    float4 sc = ((const float4*)scale)[t];
    float4 bi = ((const float4*)bias)[t];
    float4 o4;
    o4.x = (v.x - mean) * rstd * sc.x + bi.x;
    o4.y = (v.y - mean) * rstd * sc.y + bi.y;
    o4.z = (v.z - mean) * rstd * sc.z + bi.z;
    o4.w = (v.w - mean) * rstd * sc.w + bi.w;
    ((float4*)(out + (size_t)row * DIM))[t] = o4;
}

// ---------------- SGEMM: C[M,N] = A[M,K] @ B[K,N] (+epilogue) ----------------
// EPI 0: C = acc
// EPI 1: C = resid + acc + bias   (resid may alias C; in-place safe)
// EPI 2: C = gelu(acc + bias)
#define BM 128
#define BN 128
#define BK 8

__device__ __forceinline__ float gelu_exact(float v) {
    return 0.5f * v * (1.0f + erff(v * 0.70710678118654752f));
}

template<int EPI>
__global__ __launch_bounds__(256) void sgemm_kernel(
    const float* __restrict__ A, const float* __restrict__ B,
    const float* __restrict__ bias, const float* __restrict__ resid,
    float* __restrict__ C, int M, int N, int K)
{
    __shared__ float As[BK][BM + 4];   // padded: avoid STS conflicts
    __shared__ float Bs[BK][BN];

    int tid = threadIdx.x;
    int bm = blockIdx.y, bn = blockIdx.x;
    int r = tid >> 4, c = tid & 15;

    const float* Ab = A + (size_t)(bm * BM) * K;
    const float* Bb = B + bn * BN;

    int arow = tid >> 1, aseg = tid & 1;
    int brow = tid >> 5, bcol = (tid & 31) << 2;

    float acc[8][8];
    #pragma unroll
    for (int i = 0; i < 8; i++)
        #pragma unroll
        for (int j = 0; j < 8; j++) acc[i][j] = 0.f;

    float4 av = *(const float4*)(Ab + (size_t)arow * K + aseg * 4);
    float4 bv = *(const float4*)(Bb + (size_t)brow * N + bcol);

    for (int k0 = 0; k0 < K; k0 += BK) {
        As[aseg * 4 + 0][arow] = av.x;
        As[aseg * 4 + 1][arow] = av.y;
        As[aseg * 4 + 2][arow] = av.z;
        As[aseg * 4 + 3][arow] = av.w;
        *(float4*)&Bs[brow][bcol] = bv;
        __syncthreads();
        if (k0 + BK < K) {
            av = *(const float4*)(Ab + (size_t)arow * K + (k0 + BK) + aseg * 4);
            bv = *(const float4*)(Bb + (size_t)(k0 + BK + brow) * N + bcol);
        }
        #pragma unroll
        for (int kk = 0; kk < BK; kk++) {
            float a[8], b[8];
            *(float4*)(a)     = *(const float4*)&As[kk][r * 8];
            *(float4*)(a + 4) = *(const float4*)&As[kk][r * 8 + 4];
            *(float4*)(b)     = *(const float4*)&Bs[kk][c * 8];
            *(float4*)(b + 4) = *(const float4*)&Bs[kk][c * 8 + 4];
            #pragma unroll
            for (int i = 0; i < 8; i++)
                #pragma unroll
                for (int j = 0; j < 8; j++)
                    acc[i][j] += a[i] * b[j];
        }
        __syncthreads();
    }

    int gm0 = bm * BM + r * 8;
    int gn0 = bn * BN + c * 8;
    float bfrag[8];
    if (EPI >= 1) {
        #pragma unroll
        for (int j = 0; j < 8; j++) bfrag[j] = bias[gn0 + j];
    }
    #pragma unroll
    for (int i = 0; i < 8; i++) {
        size_t base = (size_t)(gm0 + i) * N + gn0;
        float out[8];
        #pragma unroll
        for (int j = 0; j < 8; j++) {
            float v = acc[i][j];
            if (EPI == 1) v += bfrag[j] + resid[base + j];
            if (EPI == 2) v = gelu_exact(v + bfrag[j]);
            out[j] = v;
        }
        *(float4*)(C + base)     = *(float4*)(out);
        *(float4*)(C + base + 4) = *(float4*)(out + 4);
    }
}

// ---------------- Attention ----------------
// grid: (SEQ/16, B*H), block 256, dynamic smem:
//   qs[16*64] + sc[16*512] + kvs[128*65]  = 70144 bytes
#define ATTN_SMEM ((16*64 + 16*512 + 128*65) * 4)

__global__ __launch_bounds__(256) void attn_kernel(
    const float* __restrict__ qkv, float* __restrict__ o)
{
    extern __shared__ float sm[];
    float* qs  = sm;                 // [16][64]
    float* sc  = qs + 16 * 64;       // [16][512]
    float* kvs = sc + 16 * 512;      // [128][65] (stride 65 -> conflict free)

    int t  = threadIdx.x;
    int bh = blockIdx.y;
    int b  = bh >> 4, h = bh & 15;
    int q0 = blockIdx.x * 16;

    const float* qbase = qkv + (size_t)(b * SEQ) * (3 * ID) + h * DHEAD;
    const float* kbase = qbase + ID;
    const float* vbase = qbase + 2 * ID;

    // load 16 query rows
    {
        int row = t >> 4, d4 = (t & 15) * 4;
        float4 v = *(const float4*)(qbase + (size_t)(q0 + row) * (3 * ID) + d4);
        *(float4*)&qs[row * 64 + d4] = v;
    }

    // ---- scores: S = Q K^T * 0.125 ----
    for (int kc = 0; kc < 4; kc++) {
        __syncthreads();
        #pragma unroll
        for (int i = 0; i < 8; i++) {
            int f = i * 256 + t;               // float4 index within 128x64 tile
            int row = f >> 4, d4 = (f & 15) * 4;
            float4 v = *(const float4*)(kbase + (size_t)(kc * 128 + row) * (3 * ID) + d4);
            kvs[row * 65 + d4 + 0] = v.x;
            kvs[row * 65 + d4 + 1] = v.y;
            kvs[row * 65 + d4 + 2] = v.z;
            kvs[row * 65 + d4 + 3] = v.w;
        }
        __syncthreads();
        #pragma unroll
        for (int i = 0; i < 8; i++) {
            int idx = i * 256 + t;
            int qi = idx >> 7, kj = idx & 127;
            const float* qrow = &qs[qi * 64];
            const float* krow = &kvs[kj * 65];
            float s = 0.f;
            #pragma unroll 16
            for (int d = 0; d < 64; d++) s += qrow[d] * krow[d];
            sc[qi * 512 + kc * 128 + kj] = s * 0.125f;
        }
    }
    __syncthreads();

    // ---- softmax: one warp per 2 rows ----
    int wid = t >> 5, lane = t & 31;
    for (int qi = wid; qi < 16; qi += 8) {
        float* srow = &sc[qi * 512];
        float m = -1e30f;
        float e[16];
        #pragma unroll
        for (int i = 0; i < 16; i++) m = fmaxf(m, srow[i * 32 + lane]);
        #pragma unroll
        for (int off = 16; off; off >>= 1) m = fmaxf(m, __shfl_xor_sync(0xffffffffu, m, off));
        float sum = 0.f;
        #pragma unroll
        for (int i = 0; i < 16; i++) { e[i] = __expf(srow[i * 32 + lane] - m); sum += e[i]; }
        #pragma unroll
        for (int off = 16; off; off >>= 1) sum += __shfl_xor_sync(0xffffffffu, sum, off);
        float inv = 1.0f / sum;
        #pragma unroll
        for (int i = 0; i < 16; i++) srow[i * 32 + lane] = e[i] * inv;
    }
    __syncthreads();

    // ---- O = P @ V ----
    float oacc[4] = {0.f, 0.f, 0.f, 0.f};
    for (int vc = 0; vc < 4; vc++) {
        #pragma unroll
        for (int i = 0; i < 8; i++) {
            int f = i * 256 + t;
            int row = f >> 4, d4 = (f & 15) * 4;
            float4 v = *(const float4*)(vbase + (size_t)(vc * 128 + row) * (3 * ID) + d4);
            kvs[row * 65 + d4 + 0] = v.x;
            kvs[row * 65 + d4 + 1] = v.y;
            kvs[row * 65 + d4 + 2] = v.z;
            kvs[row * 65 + d4 + 3] = v.w;
        }
        __syncthreads();
        #pragma unroll
        for (int i = 0; i < 4; i++) {
            int idx = i * 256 + t;
            int qi = idx >> 6, d = idx & 63;
            const float* prow = &sc[qi * 512 + vc * 128];
            float a = oacc[i];
            #pragma unroll 16
            for (int j = 0; j < 128; j++) a += prow[j] * kvs[j * 65 + d];
            oacc[i] = a;
        }
        __syncthreads();
    }
    #pragma unroll
    for (int i = 0; i < 4; i++) {
        int idx = i * 256 + t;
        int qi = idx >> 6, d = idx & 63;
        o[(size_t)(b * SEQ + q0 + qi) * ID + h * DHEAD + d] = oacc[i];
    }
}

// ---------------- driver ----------------
extern "C" void kernel_launch(void* const* d_in, const int* in_sizes, int n_in,
                              void* d_out, int out_size)
{
    const float* x_in = (const float*)d_in[0];
    const float* ln1s = (const float*)d_in[1];
    const float* ln1b = (const float*)d_in[2];
    const float* wqkv = (const float*)d_in[3];
    const float* wout = (const float*)d_in[4];
    const float* bout = (const float*)d_in[5];
    const float* ln2s = (const float*)d_in[6];
    const float* ln2b = (const float*)d_in[7];
    const float* w1   = (const float*)d_in[8];
    const float* b1   = (const float*)d_in[9];
    const float* w2   = (const float*)d_in[10];
    const float* b2   = (const float*)d_in[11];
    float* x = (float*)d_out;   // residual stream lives in d_out

    void* p;
    cudaGetSymbolAddress(&p, g_h);   float* gh   = (float*)p;
    cudaGetSymbolAddress(&p, g_qkv); float* gqkv = (float*)p;
    cudaGetSymbolAddress(&p, g_o);   float* go   = (float*)p;
    cudaGetSymbolAddress(&p, g_a);   float* ga   = (float*)p;

    cudaFuncSetAttribute(attn_kernel, cudaFuncAttributeMaxDynamicSharedMemorySize, ATTN_SMEM);

    cudaMemcpyAsync(x, x_in, (size_t)TOKENS * DIM * sizeof(float),
                    cudaMemcpyDeviceToDevice);

    for (int l = 0; l < LAYERS; l++) {
        const float* l1s = ln1s + l * DIM;
        const float* l1b = ln1b + l * DIM;
        const float* wq  = wqkv + (size_t)l * DIM * (3 * ID);
        const float* wo  = wout + (size_t)l * ID * DIM;
        const float* bo  = bout + l * DIM;
        const float* l2s = ln2s + l * DIM;
        const float* l2b = ln2b + l * DIM;
        const float* w1l = w1 + (size_t)l * DIM * FFN;
        const float* b1l = b1 + l * FFN;
        const float* w2l = w2 + (size_t)l * FFN * DIM;
        const float* b2l = b2 + l * DIM;

        // h = LN1(x)
        ln_kernel<<<TOKENS, 256>>>(x, l1s, l1b, gh);
        // qkv = h @ wqkv
        sgemm_kernel<0><<<dim3(3 * ID / BN, TOKENS / BM), 256>>>(
            gh, wq, nullptr, nullptr, gqkv, TOKENS, 3 * ID, DIM);
        // attention
        attn_kernel<<<dim3(SEQ / 16, BATCH * HEADS), 256, ATTN_SMEM>>>(gqkv, go);
        // x = x + o @ wo + bo   (in-place on x)
        sgemm_kernel<1><<<dim3(DIM / BN, TOKENS / BM), 256>>>(
            go, wo, bo, x, x, TOKENS, DIM, ID);
        // h = LN2(x)
        ln_kernel<<<TOKENS, 256>>>(x, l2s, l2b, gh);
        // a = gelu(h @ w1 + b1)
        sgemm_kernel<2><<<dim3(FFN / BN, TOKENS / BM), 256>>>(
            gh, w1l, b1l, nullptr, ga, TOKENS, FFN, DIM);
        // x = x + a @ w2 + b2   (in-place on x)
        sgemm_kernel<1><<<dim3(DIM / BN, TOKENS / BM), 256>>>(
            ga, w2l, b2l, x, x, TOKENS, DIM, FFN);
    }
}

// round 4
// speedup vs baseline: 2.3067x; 2.3067x over previous
#include <cuda_runtime.h>
#include <math.h>
#include <stdint.h>

#define LAYERS 6
#define BATCH  4
#define SEQ    512
#define DIM    1024
#define HEADS  16
#define DHEAD  64
#define FFN    4096
#define TOKENS (BATCH*SEQ)          // 2048
#define ID     (HEADS*DHEAD)        // 1024

// ---------------- scratch (allocation-guard safe) ----------------
__device__ float g_h  [TOKENS*DIM];
__device__ float g_qkv[TOKENS*3*ID];
__device__ float g_o  [TOKENS*ID];
__device__ float g_a  [(size_t)TOKENS*FFN];

// ---------------- small PTX helpers ----------------
__device__ __forceinline__ uint32_t smem_u32(const void* p) {
    uint32_t a;
    asm("{ .reg .u64 t; cvta.to.shared.u64 t, %1; cvt.u32.u64 %0, t; }" : "=r"(a) : "l"(p));
    return a;
}
__device__ __forceinline__ void cp16(uint32_t dst, const void* src) {
    asm volatile("cp.async.cg.shared.global [%0], [%1], 16;" :: "r"(dst), "l"(src));
}
__device__ __forceinline__ void cp_commit() {
    asm volatile("cp.async.commit_group;" ::: "memory");
}
template<int N> __device__ __forceinline__ void cp_wait() {
    asm volatile("cp.async.wait_group %0;" :: "n"(N) : "memory");
}
__device__ __forceinline__ uint32_t f2tf(float x) {
    uint32_t u; asm("cvt.rna.tf32.f32 %0, %1;" : "=r"(u) : "f"(x)); return u;
}
__device__ __forceinline__ void mma_tf32(float* d, const uint32_t* a, const uint32_t* b) {
    asm volatile(
        "mma.sync.aligned.m16n8k8.row.col.f32.tf32.tf32.f32 "
        "{%0,%1,%2,%3}, {%4,%5,%6,%7}, {%8,%9}, {%0,%1,%2,%3};"
        : "+f"(d[0]), "+f"(d[1]), "+f"(d[2]), "+f"(d[3])
        : "r"(a[0]), "r"(a[1]), "r"(a[2]), "r"(a[3]), "r"(b[0]), "r"(b[1]));
}

// ---------------- LayerNorm ----------------
__global__ __launch_bounds__(256) void ln_kernel(
    const float* __restrict__ x, const float* __restrict__ scale,
    const float* __restrict__ bias, float* __restrict__ out)
{
    __shared__ float wsum[8], wsq[8];
    int row = blockIdx.x, t = threadIdx.x;
    const float4* xr = (const float4*)(x + (size_t)row * DIM);
    float4 v = xr[t];
    float s  = v.x + v.y + v.z + v.w;
    float ss = v.x*v.x + v.y*v.y + v.z*v.z + v.w*v.w;
    #pragma unroll
    for (int o = 16; o; o >>= 1) {
        s  += __shfl_xor_sync(0xffffffffu, s,  o);
        ss += __shfl_xor_sync(0xffffffffu, ss, o);
    }
    if ((t & 31) == 0) { wsum[t >> 5] = s; wsq[t >> 5] = ss; }
    __syncthreads();
    float S = 0.f, SS = 0.f;
    #pragma unroll
    for (int i = 0; i < 8; i++) { S += wsum[i]; SS += wsq[i]; }
    float mean = S * (1.0f / DIM);
    float var  = SS * (1.0f / DIM) - mean * mean;
    float rstd = rsqrtf(var + 1e-5f);
    float4 sc = ((const float4*)scale)[t];
    float4 bi = ((const float4*)bias)[t];
    float4 o4;
    o4.x = (v.x - mean) * rstd * sc.x + bi.x;
    o4.y = (v.y - mean) * rstd * sc.y + bi.y;
    o4.z = (v.z - mean) * rstd * sc.z + bi.z;
    o4.w = (v.w - mean) * rstd * sc.w + bi.w;
    ((float4*)(out + (size_t)row * DIM))[t] = o4;
}

// ---------------- tf32 mma.sync GEMM ----------------
// C[M,N] = A[M,K] @ B[K,N]   (A row-major, B row-major [K][N])
// EPI 0: C = acc ; EPI 1: C = acc + bias + resid (in-place safe) ; EPI 2: C = gelu(acc + bias)
#define STAGES 4
#define APAD 20     // floats per A smem row (16 + 4)  -> bank-bijective frag loads
#define BPAD 136    // floats per B smem row (128 + 8) -> bank-bijective frag loads
#define A_STAGE_FLOATS (128 * APAD)            // 2560
#define B_STAGE_FLOATS (16 * BPAD)             // 2176
#define STAGE_FLOATS   (A_STAGE_FLOATS + B_STAGE_FLOATS)   // 4736
#define GEMM_SMEM (STAGES * STAGE_FLOATS * 4)  // 75776 bytes

__device__ __forceinline__ float gelu_exact(float v) {
    return 0.5f * v * (1.0f + erff(v * 0.70710678118654752f));
}

template<int EPI>
__global__ __launch_bounds__(128)
void tc_gemm(const float* __restrict__ A, const float* __restrict__ B,
             const float* __restrict__ bias, const float* __restrict__ resid,
             float* __restrict__ C, int N, int K)
{
    extern __shared__ float smf[];
    const uint32_t sb = smem_u32(smf);
    const int tid  = threadIdx.x;
    const int lane = tid & 31, wid = tid >> 5;
    const int wm = wid & 1, wn = wid >> 1;
    const int m0 = blockIdx.y * 128;
    const int n0 = blockIdx.x * 128;

    // gmem -> smem fill for one stage (BK=16)
    auto fill = [&](int s, int k0) {
        float* As = smf + s * STAGE_FLOATS;
        float* Bs = As + A_STAGE_FLOATS;
        uint32_t ab = sb + (uint32_t)(s * STAGE_FLOATS) * 4;
        uint32_t bb = ab + A_STAGE_FLOATS * 4;
        #pragma unroll
        for (int it = 0; it < 4; it++) {            // A: 128 rows x 16 cols
            int idx = it * 128 + tid;
            int r = idx >> 2, sg = idx & 3;
            cp16(ab + (uint32_t)(r * APAD + sg * 4) * 4,
                 A + (size_t)(m0 + r) * K + k0 + sg * 4);
        }
        #pragma unroll
        for (int it = 0; it < 4; it++) {            // B: 16 rows x 128 cols
            int idx = it * 128 + tid;
            int kk = idx >> 5, sg = idx & 31;
            cp16(bb + (uint32_t)(kk * BPAD + sg * 4) * 4,
                 B + (size_t)(k0 + kk) * N + n0 + sg * 4);
        }
        (void)As; (void)Bs;
    };

    float acc[4][8][4];
    #pragma unroll
    for (int i = 0; i < 4; i++)
        #pragma unroll
        for (int j = 0; j < 8; j++)
            #pragma unroll
            for (int q = 0; q < 4; q++) acc[i][j][q] = 0.f;

    const int NK = K >> 4;

    // prologue: stages 0..STAGES-2
    #pragma unroll
    for (int p = 0; p < STAGES - 1; p++) { fill(p, p * 16); cp_commit(); }

    const int fr = lane >> 2, fc = lane & 3;

    for (int i = 0; i < NK; i++) {
        cp_wait<STAGES - 2>();
        __syncthreads();
        if (i + STAGES - 1 < NK) fill((i + STAGES - 1) & (STAGES - 1), (i + STAGES - 1) * 16);
        cp_commit();

        const float* As = smf + (i & (STAGES - 1)) * STAGE_FLOATS;
        const float* Bs = As + A_STAGE_FLOATS;

        #pragma unroll
        for (int ks = 0; ks < 2; ks++) {
            uint32_t af[4][4], bf[8][2];
            #pragma unroll
            for (int mt = 0; mt < 4; mt++) {
                const float* ap = As + (wm * 64 + mt * 16 + fr) * APAD + ks * 8 + fc;
                af[mt][0] = f2tf(ap[0]);
                af[mt][1] = f2tf(ap[8 * APAD]);
                af[mt][2] = f2tf(ap[4]);
                af[mt][3] = f2tf(ap[8 * APAD + 4]);
            }
            #pragma unroll
            for (int nt = 0; nt < 8; nt++) {
                const float* bp = Bs + (ks * 8 + fc) * BPAD + wn * 64 + nt * 8 + fr;
                bf[nt][0] = f2tf(bp[0]);
                bf[nt][1] = f2tf(bp[4 * BPAD]);
            }
            #pragma unroll
            for (int mt = 0; mt < 4; mt++)
                #pragma unroll
                for (int nt = 0; nt < 8; nt++)
                    mma_tf32(acc[mt][nt], af[mt], bf[nt]);
        }
        __syncthreads();
    }

    // ---- epilogue ----
    #pragma unroll
    for (int mt = 0; mt < 4; mt++) {
        int row = m0 + wm * 64 + mt * 16 + fr;
        #pragma unroll
        for (int nt = 0; nt < 8; nt++) {
            int col = n0 + wn * 64 + nt * 8 + fc * 2;
            float* d = acc[mt][nt];
            size_t i0 = (size_t)row * N + col;
            size_t i1 = (size_t)(row + 8) * N + col;
            float o0 = d[0], o1 = d[1], o2 = d[2], o3 = d[3];
            if (EPI == 1) {
                float bx = bias[col], by = bias[col + 1];
                o0 += bx + resid[i0]; o1 += by + resid[i0 + 1];
                o2 += bx + resid[i1]; o3 += by + resid[i1 + 1];
            }
            if (EPI == 2) {
                float bx = bias[col], by = bias[col + 1];
                o0 = gelu_exact(o0 + bx); o1 = gelu_exact(o1 + by);
                o2 = gelu_exact(o2 + bx); o3 = gelu_exact(o3 + by);
            }
            *(float2*)(C + i0) = make_float2(o0, o1);
            *(float2*)(C + i1) = make_float2(o2, o3);
        }
    }
}

// ---------------- Attention (unchanged, validated in R1) ----------------
#define ATTN_SMEM ((16*64 + 16*512 + 128*65) * 4)

__global__ __launch_bounds__(256) void attn_kernel(
    const float* __restrict__ qkv, float* __restrict__ o)
{
    extern __shared__ float sm[];
    float* qs  = sm;
    float* sc  = qs + 16 * 64;
    float* kvs = sc + 16 * 512;

    int t  = threadIdx.x;
    int bh = blockIdx.y;
    int b  = bh >> 4, h = bh & 15;
    int q0 = blockIdx.x * 16;

    const float* qbase = qkv + (size_t)(b * SEQ) * (3 * ID) + h * DHEAD;
    const float* kbase = qbase + ID;
    const float* vbase = qbase + 2 * ID;

    {
        int row = t >> 4, d4 = (t & 15) * 4;
        float4 v = *(const float4*)(qbase + (size_t)(q0 + row) * (3 * ID) + d4);
        *(float4*)&qs[row * 64 + d4] = v;
    }

    for (int kc = 0; kc < 4; kc++) {
        __syncthreads();
        #pragma unroll
        for (int i = 0; i < 8; i++) {
            int f = i * 256 + t;
            int row = f >> 4, d4 = (f & 15) * 4;
            float4 v = *(const float4*)(kbase + (size_t)(kc * 128 + row) * (3 * ID) + d4);
            kvs[row * 65 + d4 + 0] = v.x;
            kvs[row * 65 + d4 + 1] = v.y;
            kvs[row * 65 + d4 + 2] = v.z;
            kvs[row * 65 + d4 + 3] = v.w;
        }
        __syncthreads();
        #pragma unroll
        for (int i = 0; i < 8; i++) {
            int idx = i * 256 + t;
            int qi = idx >> 7, kj = idx & 127;
            const float* qrow = &qs[qi * 64];
            const float* krow = &kvs[kj * 65];
            float s = 0.f;
            #pragma unroll 16
            for (int d = 0; d < 64; d++) s += qrow[d] * krow[d];
            sc[qi * 512 + kc * 128 + kj] = s * 0.125f;
        }
    }
    __syncthreads();

    int wid = t >> 5, lane = t & 31;
    for (int qi = wid; qi < 16; qi += 8) {
        float* srow = &sc[qi * 512];
        float m = -1e30f;
        float e[16];
        #pragma unroll
        for (int i = 0; i < 16; i++) m = fmaxf(m, srow[i * 32 + lane]);
        #pragma unroll
        for (int off = 16; off; off >>= 1) m = fmaxf(m, __shfl_xor_sync(0xffffffffu, m, off));
        float sum = 0.f;
        #pragma unroll
        for (int i = 0; i < 16; i++) { e[i] = __expf(srow[i * 32 + lane] - m); sum += e[i]; }
        #pragma unroll
        for (int off = 16; off; off >>= 1) sum += __shfl_xor_sync(0xffffffffu, sum, off);
        float inv = 1.0f / sum;
        #pragma unroll
        for (int i = 0; i < 16; i++) srow[i * 32 + lane] = e[i] * inv;
    }
    __syncthreads();

    float oacc[4] = {0.f, 0.f, 0.f, 0.f};
    for (int vc = 0; vc < 4; vc++) {
        #pragma unroll
        for (int i = 0; i < 8; i++) {
            int f = i * 256 + t;
            int row = f >> 4, d4 = (f & 15) * 4;
            float4 v = *(const float4*)(vbase + (size_t)(vc * 128 + row) * (3 * ID) + d4);
            kvs[row * 65 + d4 + 0] = v.x;
            kvs[row * 65 + d4 + 1] = v.y;
            kvs[row * 65 + d4 + 2] = v.z;
            kvs[row * 65 + d4 + 3] = v.w;
        }
        __syncthreads();
        #pragma unroll
        for (int i = 0; i < 4; i++) {
            int idx = i * 256 + t;
            int qi = idx >> 6, d = idx & 63;
            const float* prow = &sc[qi * 512 + vc * 128];
            float a = oacc[i];
            #pragma unroll 16
            for (int j = 0; j < 128; j++) a += prow[j] * kvs[j * 65 + d];
            oacc[i] = a;
        }
        __syncthreads();
    }
    #pragma unroll
    for (int i = 0; i < 4; i++) {
        int idx = i * 256 + t;
        int qi = idx >> 6, d = idx & 63;
        o[(size_t)(b * SEQ + q0 + qi) * ID + h * DHEAD + d] = oacc[i];
    }
}

// ---------------- driver ----------------
extern "C" void kernel_launch(void* const* d_in, const int* in_sizes, int n_in,
                              void* d_out, int out_size)
{
    const float* x_in = (const float*)d_in[0];
    const float* ln1s = (const float*)d_in[1];
    const float* ln1b = (const float*)d_in[2];
    const float* wqkv = (const float*)d_in[3];
    const float* wout = (const float*)d_in[4];
    const float* bout = (const float*)d_in[5];
    const float* ln2s = (const float*)d_in[6];
    const float* ln2b = (const float*)d_in[7];
    const float* w1   = (const float*)d_in[8];
    const float* b1   = (const float*)d_in[9];
    const float* w2   = (const float*)d_in[10];
    const float* b2   = (const float*)d_in[11];
    float* x = (float*)d_out;

    void* p;
    cudaGetSymbolAddress(&p, g_h);   float* gh   = (float*)p;
    cudaGetSymbolAddress(&p, g_qkv); float* gqkv = (float*)p;
    cudaGetSymbolAddress(&p, g_o);   float* go   = (float*)p;
    cudaGetSymbolAddress(&p, g_a);   float* ga   = (float*)p;

    cudaFuncSetAttribute(attn_kernel, cudaFuncAttributeMaxDynamicSharedMemorySize, ATTN_SMEM);
    cudaFuncSetAttribute(tc_gemm<0>, cudaFuncAttributeMaxDynamicSharedMemorySize, GEMM_SMEM);
    cudaFuncSetAttribute(tc_gemm<1>, cudaFuncAttributeMaxDynamicSharedMemorySize, GEMM_SMEM);
    cudaFuncSetAttribute(tc_gemm<2>, cudaFuncAttributeMaxDynamicSharedMemorySize, GEMM_SMEM);

    cudaMemcpyAsync(x, x_in, (size_t)TOKENS * DIM * sizeof(float),
                    cudaMemcpyDeviceToDevice);

    for (int l = 0; l < LAYERS; l++) {
        const float* l1s = ln1s + l * DIM;
        const float* l1b = ln1b + l * DIM;
        const float* wq  = wqkv + (size_t)l * DIM * (3 * ID);
        const float* wo  = wout + (size_t)l * ID * DIM;
        const float* bo  = bout + l * DIM;
        const float* l2s = ln2s + l * DIM;
        const float* l2b = ln2b + l * DIM;
        const float* w1l = w1 + (size_t)l * DIM * FFN;
        const float* b1l = b1 + l * FFN;
        const float* w2l = w2 + (size_t)l * FFN * DIM;
        const float* b2l = b2 + l * DIM;

        // h = LN1(x)
        ln_kernel<<<TOKENS, 256>>>(x, l1s, l1b, gh);
        // qkv = h @ wqkv
        tc_gemm<0><<<dim3(3 * ID / 128, TOKENS / 128), 128, GEMM_SMEM>>>(
            gh, wq, nullptr, nullptr, gqkv, 3 * ID, DIM);
        // attention
        attn_kernel<<<dim3(SEQ / 16, BATCH * HEADS), 256, ATTN_SMEM>>>(gqkv, go);
        // x = x + o @ wo + bo
        tc_gemm<1><<<dim3(DIM / 128, TOKENS / 128), 128, GEMM_SMEM>>>(
            go, wo, bo, x, x, DIM, ID);
        // h = LN2(x)
        ln_kernel<<<TOKENS, 256>>>(x, l2s, l2b, gh);
        // a = gelu(h @ w1 + b1)
        tc_gemm<2><<<dim3(FFN / 128, TOKENS / 128), 128, GEMM_SMEM>>>(
            gh, w1l, b1l, nullptr, ga, FFN, DIM);
        // x = x + a @ w2 + b2
        tc_gemm<1><<<dim3(DIM / 128, TOKENS / 128), 128, GEMM_SMEM>>>(
            ga, w2l, b2l, x, x, DIM, FFN);
    }
}